// round 16
// baseline (speedup 1.0000x reference)
#include <cuda_runtime.h>
#include <stdint.h>

// Problem constants: B=32, T=4, L=256, D=768
#define DDIM 768
#define MTOT 32768
#define NPOS 8192
#define BP 132    // B-tile smem row pitch
#define AP 264    // duplicated A-tile smem row pitch
#define LNP 776   // ln_lif smem row pitch

typedef unsigned long long ull;

__device__ float    g_Y[(size_t)MTOT * DDIM];      // GEMM out / LN in, tble order
__device__ float    g_Wt[DDIM * DDIM];             // W2 transposed: g_Wt[d][e]
__device__ uint16_t g_idx[(size_t)MTOT * DDIM];    // per-row ascending nonzero d list
__device__ int4     g_cnt[MTOT];                   // x=c1(<320), y=c2(<640), z=nnz

// Packed f32x2 ops (each half independent IEEE-RN -> bit-exact chains)
#define FMA2(d, a, b, c) \
    asm("fma.rn.f32x2 %0, %1, %2, %3;" : "=l"(d) : "l"(a), "l"(b), "l"(c))
#define ADD2(d, a, b) \
    asm("add.rn.f32x2 %0, %1, %2;" : "=l"(d) : "l"(a), "l"(b))
#define UNPACK2(lo, hi, s) \
    asm("mov.b64 {%0, %1}, %2;" : "=r"(lo), "=r"(hi) : "l"(s))

// B-tile swizzle: column c -> slot jp*32 + ((tx+4*jp)&15)*2 + lo
__device__ __forceinline__ int bpos(int c) {
    int tx = c >> 3, jp = (c & 7) >> 1, lo = c & 1;
    return jp * 32 + (((tx + 4 * jp) & 15) << 1) + lo;
}

// ---------------------------------------------------------------------------
// Dense SGEMM (Eigen gebp / XLA:CPU bit-exact): panels d=[0,320),[320,640),
// [640,768); ascending single-accumulator chain per panel via fma.rn.f32x2.
// A tile stored DUPLICATED (row m at slots 2m,2m+1) so the packed (a,a)
// operand is one LDS.64 -- no PACK2 MOVs in the mainloop (16 issue slots/k
// saved). B tile conflict-free swizzled; totals in dynamic smem (2 CTAs/SM).
// ---------------------------------------------------------------------------
__global__ __launch_bounds__(256, 2) void sgemm_kernel(
    const float* __restrict__ A, const float* __restrict__ W,
    const float* __restrict__ bias)
{
    __shared__ float As[2][8][AP];
    __shared__ float Bs[2][8][BP];
    extern __shared__ ull totsm[];     // [32][256]

    int tid = threadIdx.x;
    int bx = blockIdx.x;
    int by = blockIdx.y;

    int lrow = tid >> 1;
    int lkk  = (tid & 1) << 2;
    int wpos = bpos(lrow);

    int arow = (by << 7) + lrow;
    int t = arow >> 13;
    int b = (arow >> 8) & 31;
    int l = arow & 255;
    int srow = (b << 10) + (t << 8) + l;

    const float* aptr = A + (size_t)srow * DDIM + lkk;
    const float* bptr = W + (size_t)((bx << 7) + lrow) * DDIM + lkk;

    ull acc2[8][4];
    #pragma unroll
    for (int i = 0; i < 8; i++)
        #pragma unroll
        for (int j = 0; j < 4; j++) acc2[i][j] = 0ull;

    {
        float4 a4 = *(const float4*)aptr;
        float4 b4 = *(const float4*)bptr;
        *(float2*)&As[0][lkk + 0][2 * lrow] = make_float2(a4.x, a4.x);
        *(float2*)&As[0][lkk + 1][2 * lrow] = make_float2(a4.y, a4.y);
        *(float2*)&As[0][lkk + 2][2 * lrow] = make_float2(a4.z, a4.z);
        *(float2*)&As[0][lkk + 3][2 * lrow] = make_float2(a4.w, a4.w);
        Bs[0][lkk + 0][wpos] = b4.x; Bs[0][lkk + 1][wpos] = b4.y;
        Bs[0][lkk + 2][wpos] = b4.z; Bs[0][lkk + 3][wpos] = b4.w;
    }
    __syncthreads();

    int tx = tid & 15;
    int ty = tid >> 4;
    int rb[4];
    #pragma unroll
    for (int jp = 0; jp < 4; jp++)
        rb[jp] = jp * 32 + (((tx + 4 * jp) & 15) << 1);

    const int KT = DDIM / 8;  // 96; fold after kt=39 (d=320) and kt=79 (d=640)
    for (int kt = 0; kt < KT; kt++) {
        int cur = kt & 1;
        float4 na, nb;
        if (kt < KT - 1) {
            na = *(const float4*)(aptr + (kt + 1) * 8);
            nb = *(const float4*)(bptr + (kt + 1) * 8);
        }
        #pragma unroll
        for (int k = 0; k < 8; k++) {
            ull aa[8], b2[4];
            const ull* ap = (const ull*)&As[cur][k][ty * 16];
            #pragma unroll
            for (int i = 0; i < 8; i++) aa[i] = ap[i];
            #pragma unroll
            for (int jp = 0; jp < 4; jp++)
                b2[jp] = *(const ull*)&Bs[cur][k][rb[jp]];
            #pragma unroll
            for (int i = 0; i < 8; i++)
                #pragma unroll
                for (int jp = 0; jp < 4; jp++)
                    FMA2(acc2[i][jp], aa[i], b2[jp], acc2[i][jp]);
        }
        if (kt == 39) {
            #pragma unroll
            for (int i = 0; i < 8; i++)
                #pragma unroll
                for (int jp = 0; jp < 4; jp++) {
                    totsm[(i * 4 + jp) * 256 + tid] = acc2[i][jp];
                    acc2[i][jp] = 0ull;
                }
        }
        if (kt == 79) {
            #pragma unroll
            for (int i = 0; i < 8; i++)
                #pragma unroll
                for (int jp = 0; jp < 4; jp++) {
                    ull tv = totsm[(i * 4 + jp) * 256 + tid];
                    ADD2(tv, tv, acc2[i][jp]);
                    totsm[(i * 4 + jp) * 256 + tid] = tv;
                    acc2[i][jp] = 0ull;
                }
        }
        if (kt < KT - 1) {
            int nxt = cur ^ 1;
            *(float2*)&As[nxt][lkk + 0][2 * lrow] = make_float2(na.x, na.x);
            *(float2*)&As[nxt][lkk + 1][2 * lrow] = make_float2(na.y, na.y);
            *(float2*)&As[nxt][lkk + 2][2 * lrow] = make_float2(na.z, na.z);
            *(float2*)&As[nxt][lkk + 3][2 * lrow] = make_float2(na.w, na.w);
            Bs[nxt][lkk + 0][wpos] = nb.x; Bs[nxt][lkk + 1][wpos] = nb.y;
            Bs[nxt][lkk + 2][wpos] = nb.z; Bs[nxt][lkk + 3][wpos] = nb.w;
            __syncthreads();
        }
    }

    int e0 = (bx << 7) + tx * 8;
    #pragma unroll
    for (int i = 0; i < 8; i++) {
        int r = (by << 7) + ty * 8 + i;
        float* cp = g_Y + (size_t)r * DDIM + e0;
        #pragma unroll
        for (int jp = 0; jp < 4; jp++) {
            ull tv = totsm[(i * 4 + jp) * 256 + tid];
            unsigned tl, th, al, ah;
            UNPACK2(tl, th, tv);
            UNPACK2(al, ah, acc2[i][jp]);
            float v0 = __fadd_rn(__uint_as_float(tl), __uint_as_float(al));
            float v1 = __fadd_rn(__uint_as_float(th), __uint_as_float(ah));
            cp[2 * jp]     = __fadd_rn(v0, bias[e0 + 2 * jp]);
            cp[2 * jp + 1] = __fadd_rn(v1, bias[e0 + 2 * jp + 1]);
        }
    }
}

// ---------------------------------------------------------------------------
// W2 transpose, 3 partial launches (keeps sgemm at launch index 3 for ncu).
// ---------------------------------------------------------------------------
__global__ void transpose_kernel(const float* __restrict__ W, int part)
{
    __shared__ float tile[32][33];
    int bx = (blockIdx.x + part * 8) << 5, by = blockIdx.y << 5;
    int x = bx + threadIdx.x;
    #pragma unroll
    for (int i = 0; i < 32; i += 8)
        tile[threadIdx.y + i][threadIdx.x] =
            W[(size_t)(by + threadIdx.y + i) * DDIM + x];
    __syncthreads();
    int x2 = by + threadIdx.x;
    #pragma unroll
    for (int i = 0; i < 32; i += 8)
        g_Wt[(size_t)(bx + threadIdx.y + i) * DDIM + x2] =
            tile[threadIdx.x][threadIdx.y + i];
}

// ---------------------------------------------------------------------------
// Fused LayerNorm + LIF (round-15 config): block = 8 positions (32 rows);
// warp 0 runs all 32 strict XLA:CPU stats chains (one row per lane,
// per-row op order unchanged -> bit-exact); warp w runs position w's LIF.
// ---------------------------------------------------------------------------
__global__ __launch_bounds__(256) void ln_lif_kernel(
    const float* __restrict__ gamma, const float* __restrict__ beta,
    float* __restrict__ outp, int final_out)
{
    extern __shared__ float sm[];      // [32 rows][LNP]
    __shared__ float smu[32], srs[32];
    int warp = threadIdx.x >> 5, lane = threadIdx.x & 31;
    int p = (blockIdx.x << 3) + warp;
    int b = p >> 8, l = p & 255;

    float g[24], bb[24], v[24];
    #pragma unroll
    for (int j = 0; j < 24; j++) {
        g[j]  = gamma[lane + (j << 5)];
        bb[j] = beta[lane + (j << 5)];
        v[j]  = 0.f;
    }

    #pragma unroll
    for (int t = 0; t < 4; t++) {
        const float4* row4 = (const float4*)(g_Y + (size_t)(t * NPOS + p) * DDIM);
        float* dst = sm + ((warp << 2) + t) * LNP;
        #pragma unroll
        for (int j = 0; j < 6; j++) {
            float4 x4 = row4[lane + (j << 5)];
            *(float4*)(dst + 4 * (lane + (j << 5))) = x4;
        }
    }
    __syncthreads();

    if (warp == 0) {
        const float* mrow = sm + lane * LNP;
        float acc = 0.f;
        #pragma unroll 8
        for (int d = 0; d < DDIM; d++)
            acc = __fadd_rn(acc, mrow[d]);
        float mu = __fdiv_rn(acc, 768.0f);
        float ssq = 0.f;
        #pragma unroll 8
        for (int d = 0; d < DDIM; d++) {
            float df = __fadd_rn(mrow[d], -mu);
            ssq = __fadd_rn(ssq, __fmul_rn(df, df));
        }
        float var = __fdiv_rn(ssq, 768.0f);
        smu[lane] = mu;
        srs[lane] = __fdiv_rn(1.0f, __fsqrt_rn(__fadd_rn(var, 1e-5f)));
    }
    __syncthreads();

    for (int t = 0; t < 4; t++) {
        int r = t * NPOS + p;
        const float* row = sm + ((warp << 2) + t) * LNP;
        float mu   = smu[(warp << 2) + t];
        float rstd = srs[(warp << 2) + t];

        if (final_out) {
            float* dst = outp + (size_t)((((b << 2) + t) << 8) + l) * DDIM;
            #pragma unroll
            for (int j = 0; j < 24; j++) {
                int d = lane + (j << 5);
                float h = __fadd_rn(
                    __fmul_rn(__fmul_rn(__fadd_rn(row[d], -mu), rstd), g[j]), bb[j]);
                float dlt = __fmul_rn(__fadd_rn(h, -v[j]), 0.5f);
                v[j] = __fadd_rn(v[j], dlt);
                float s = (v[j] >= 1.0f) ? 1.0f : 0.0f;
                dst[d] = s;
                v[j] = __fmul_rn(v[j], __fadd_rn(1.0f, -s));
            }
        } else {
            uint16_t* ip = g_idx + (size_t)r * DDIM;
            int base = 0, c1 = 0, c2 = 0;
            #pragma unroll
            for (int j = 0; j < 24; j++) {      // chunk j covers d=[32j,32j+32)
                int d = lane + (j << 5);
                float h = __fadd_rn(
                    __fmul_rn(__fmul_rn(__fadd_rn(row[d], -mu), rstd), g[j]), bb[j]);
                float dlt = __fmul_rn(__fadd_rn(h, -v[j]), 0.5f);
                v[j] = __fadd_rn(v[j], dlt);
                float s = (v[j] >= 1.0f) ? 1.0f : 0.0f;
                unsigned msk = __ballot_sync(0xffffffffu, s == 1.0f);
                if (s == 1.0f) {
                    int pos = base + __popc(msk & ((1u << lane) - 1u));
                    ip[pos] = (uint16_t)d;
                }
                base += __popc(msk);
                v[j] = __fmul_rn(v[j], __fadd_rn(1.0f, -s));
                if (j == 9)  c1 = base;   // d<320 boundary
                if (j == 19) c2 = base;   // d<640 boundary
            }
            if (lane == 0) g_cnt[r] = make_int4(c1, c2, base, 0);
        }
    }
}

// ---------------------------------------------------------------------------
// Sparse layer-2 GEMM (round-15 config): one warp per (row, e-half).
// ---------------------------------------------------------------------------
__global__ __launch_bounds__(256) void spmm_kernel(const float* __restrict__ bias)
{
    int warp = threadIdx.x >> 5, lane = threadIdx.x & 31;
    int gw = (blockIdx.x << 3) + warp;
    int r = gw >> 1;
    int eoff = (gw & 1) * 96;

    int4 cnt = g_cnt[r];
    int bounds[4] = {0, cnt.x, cnt.y, cnt.z};
    const uint16_t* idx = g_idx + (size_t)r * DDIM;

    float4 tot[3];
    #pragma unroll
    for (int j = 0; j < 3; j++) tot[j] = make_float4(0.f, 0.f, 0.f, 0.f);

    #pragma unroll
    for (int pnl = 0; pnl < 3; pnl++) {
        float4 pan[3];
        #pragma unroll
        for (int j = 0; j < 3; j++) pan[j] = make_float4(0.f, 0.f, 0.f, 0.f);
        int lo = bounds[pnl], hi = bounds[pnl + 1];
        for (int kb = lo; kb < hi; kb += 32) {
            int n = min(32, hi - kb);
            int myd = (kb + lane < hi) ? (int)idx[kb + lane] : 0;
            for (int kk = 0; kk < n; kk++) {
                int d = __shfl_sync(0xffffffffu, myd, kk);
                const float4* w = (const float4*)(g_Wt + d * DDIM) + eoff;
                #pragma unroll
                for (int j = 0; j < 3; j++) {
                    float4 w4 = w[lane + (j << 5)];
                    pan[j].x = __fadd_rn(pan[j].x, w4.x);
                    pan[j].y = __fadd_rn(pan[j].y, w4.y);
                    pan[j].z = __fadd_rn(pan[j].z, w4.z);
                    pan[j].w = __fadd_rn(pan[j].w, w4.w);
                }
            }
        }
        #pragma unroll
        for (int j = 0; j < 3; j++) {
            tot[j].x = __fadd_rn(tot[j].x, pan[j].x);
            tot[j].y = __fadd_rn(tot[j].y, pan[j].y);
            tot[j].z = __fadd_rn(tot[j].z, pan[j].z);
            tot[j].w = __fadd_rn(tot[j].w, pan[j].w);
        }
    }

    float4* orow = (float4*)(g_Y + (size_t)r * DDIM) + eoff;
    const float4* b4 = (const float4*)bias + eoff;
    #pragma unroll
    for (int j = 0; j < 3; j++) {
        int e4 = lane + (j << 5);
        float4 bbv = b4[e4];
        float4 o;
        o.x = __fadd_rn(tot[j].x, bbv.x);
        o.y = __fadd_rn(tot[j].y, bbv.y);
        o.z = __fadd_rn(tot[j].z, bbv.z);
        o.w = __fadd_rn(tot[j].w, bbv.w);
        orow[e4] = o;
    }
}

// ---------------------------------------------------------------------------
extern "C" void kernel_launch(void* const* d_in, const int* in_sizes, int n_in,
                              void* d_out, int out_size)
{
    const float* x   = (const float*)d_in[0];
    const float* W1  = (const float*)d_in[1];
    const float* b1  = (const float*)d_in[2];
    const float* g1  = (const float*)d_in[3];
    const float* be1 = (const float*)d_in[4];
    const float* W2  = (const float*)d_in[5];
    const float* b2  = (const float*)d_in[6];
    const float* g2  = (const float*)d_in[7];
    const float* be2 = (const float*)d_in[8];
    float* out = (float*)d_out;

    const int SG_SMEM = 32 * 256 * 8;       // 65536 B (sgemm tot partials)
    const int LN_SMEM = 32 * LNP * 4;       // 99328 B (32 rows)
    cudaFuncSetAttribute(sgemm_kernel,
                         cudaFuncAttributeMaxDynamicSharedMemorySize, SG_SMEM);
    cudaFuncSetAttribute(ln_lif_kernel,
                         cudaFuncAttributeMaxDynamicSharedMemorySize, LN_SMEM);

    dim3 gg(DDIM / 128, MTOT / 128);   // (6, 256)

    transpose_kernel<<<dim3(8, 24), dim3(32, 8)>>>(W2, 0);
    transpose_kernel<<<dim3(8, 24), dim3(32, 8)>>>(W2, 1);
    transpose_kernel<<<dim3(8, 24), dim3(32, 8)>>>(W2, 2);
    sgemm_kernel<<<gg, 256, SG_SMEM>>>(x, W1, b1);                // ncu idx 3
    ln_lif_kernel<<<NPOS / 8, 256, LN_SMEM>>>(g1, be1, nullptr, 0);
    spmm_kernel<<<MTOT / 4, 256>>>(b2);
    ln_lif_kernel<<<NPOS / 8, 256, LN_SMEM>>>(g2, be2, out, 1);
}

// round 17
// speedup vs baseline: 1.2180x; 1.2180x over previous
#include <cuda_runtime.h>
#include <stdint.h>

// Problem constants: B=32, T=4, L=256, D=768
#define DDIM 768
#define MTOT 32768
#define NPOS 8192
#define BP 132    // smem tile row pitch
#define LNP 776   // ln_lif smem row pitch

typedef unsigned long long ull;

__device__ float    g_Y[(size_t)MTOT * DDIM];      // GEMM out / LN in, tble order
__device__ float    g_Wt[DDIM * DDIM];             // W2 transposed: g_Wt[d][e]
__device__ uint16_t g_idx[(size_t)MTOT * DDIM];    // per-row ascending nonzero d list
__device__ int4     g_cnt[MTOT];                   // x=c1(<320), y=c2(<640), z=nnz

// Packed f32x2 ops (each half independent IEEE-RN -> bit-exact chains)
#define FMA2(d, a, b, c) \
    asm("fma.rn.f32x2 %0, %1, %2, %3;" : "=l"(d) : "l"(a), "l"(b), "l"(c))
#define ADD2(d, a, b) \
    asm("add.rn.f32x2 %0, %1, %2;" : "=l"(d) : "l"(a), "l"(b))
#define PACK2(d, lo, hi) \
    asm("mov.b64 %0, {%1, %2};" : "=l"(d) : "r"(lo), "r"(hi))
#define UNPACK2(lo, hi, s) \
    asm("mov.b64 {%0, %1}, %2;" : "=r"(lo), "=r"(hi) : "l"(s))

// B-tile chunked layout: column c -> slot ((c>>2)&1)*64 + (c>>3)*4 + (c&3).
// Thread tx reads its 8 columns as TWO LDS.128 at [tx*4] and [64+tx*4]:
// 16 distinct 16B chunks spanning 256B -> conflict-free, 4 wavefronts/k
// (vs 8 with LDS.64), pairs land aligned for FMA2.
__device__ __forceinline__ int bpos(int c) {
    return ((c >> 2) & 1) * 64 + (c >> 3) * 4 + (c & 3);
}

// ---------------------------------------------------------------------------
// Dense SGEMM (Eigen gebp / XLA:CPU bit-exact): panels d=[0,320),[320,640),
// [640,768); ascending single-accumulator chain per panel via fma.rn.f32x2;
// totals in dynamic smem (2 CTAs/SM); chunked conflict-free B layout.
// ---------------------------------------------------------------------------
__global__ __launch_bounds__(256, 2) void sgemm_kernel(
    const float* __restrict__ A, const float* __restrict__ W,
    const float* __restrict__ bias)
{
    __shared__ float As[2][8][BP];
    __shared__ float Bs[2][8][BP];
    extern __shared__ ull totsm[];     // [32][256]

    int tid = threadIdx.x;
    int bx = blockIdx.x;
    int by = blockIdx.y;

    int lrow = tid >> 1;
    int lkk  = (tid & 1) << 2;
    int wpos = bpos(lrow);

    int arow = (by << 7) + lrow;
    int t = arow >> 13;
    int b = (arow >> 8) & 31;
    int l = arow & 255;
    int srow = (b << 10) + (t << 8) + l;

    const float* aptr = A + (size_t)srow * DDIM + lkk;
    const float* bptr = W + (size_t)((bx << 7) + lrow) * DDIM + lkk;

    ull acc2[8][4];
    #pragma unroll
    for (int i = 0; i < 8; i++)
        #pragma unroll
        for (int j = 0; j < 4; j++) acc2[i][j] = 0ull;

    {
        float4 a4 = *(const float4*)aptr;
        float4 b4 = *(const float4*)bptr;
        As[0][lkk + 0][lrow] = a4.x; As[0][lkk + 1][lrow] = a4.y;
        As[0][lkk + 2][lrow] = a4.z; As[0][lkk + 3][lrow] = a4.w;
        Bs[0][lkk + 0][wpos] = b4.x; Bs[0][lkk + 1][wpos] = b4.y;
        Bs[0][lkk + 2][wpos] = b4.z; Bs[0][lkk + 3][wpos] = b4.w;
    }
    __syncthreads();

    int tx = tid & 15;
    int ty = tid >> 4;

    const int KT = DDIM / 8;  // 96; fold after kt=39 (d=320) and kt=79 (d=640)
    for (int kt = 0; kt < KT; kt++) {
        int cur = kt & 1;
        float4 na, nb;
        if (kt < KT - 1) {
            na = *(const float4*)(aptr + (kt + 1) * 8);
            nb = *(const float4*)(bptr + (kt + 1) * 8);
        }
        #pragma unroll
        for (int k = 0; k < 8; k++) {
            float a[8];
            *(float4*)(a)     = *(const float4*)&As[cur][k][ty * 8];
            *(float4*)(a + 4) = *(const float4*)&As[cur][k][ty * 8 + 4];
            ulonglong2 bb0 = *(const ulonglong2*)&Bs[cur][k][tx * 4];
            ulonglong2 bb1 = *(const ulonglong2*)&Bs[cur][k][64 + tx * 4];
            ull b2[4];
            b2[0] = bb0.x; b2[1] = bb0.y; b2[2] = bb1.x; b2[3] = bb1.y;
            ull aa[8];
            #pragma unroll
            for (int i = 0; i < 8; i++) {
                unsigned ai = __float_as_uint(a[i]);
                PACK2(aa[i], ai, ai);
            }
            #pragma unroll
            for (int i = 0; i < 8; i++)
                #pragma unroll
                for (int jp = 0; jp < 4; jp++)
                    FMA2(acc2[i][jp], aa[i], b2[jp], acc2[i][jp]);
        }
        if (kt == 39) {
            #pragma unroll
            for (int i = 0; i < 8; i++)
                #pragma unroll
                for (int jp = 0; jp < 4; jp++) {
                    totsm[(i * 4 + jp) * 256 + tid] = acc2[i][jp];
                    acc2[i][jp] = 0ull;
                }
        }
        if (kt == 79) {
            #pragma unroll
            for (int i = 0; i < 8; i++)
                #pragma unroll
                for (int jp = 0; jp < 4; jp++) {
                    ull tv = totsm[(i * 4 + jp) * 256 + tid];
                    ADD2(tv, tv, acc2[i][jp]);
                    totsm[(i * 4 + jp) * 256 + tid] = tv;
                    acc2[i][jp] = 0ull;
                }
        }
        if (kt < KT - 1) {
            int nxt = cur ^ 1;
            As[nxt][lkk + 0][lrow] = na.x; As[nxt][lkk + 1][lrow] = na.y;
            As[nxt][lkk + 2][lrow] = na.z; As[nxt][lkk + 3][lrow] = na.w;
            Bs[nxt][lkk + 0][wpos] = nb.x; Bs[nxt][lkk + 1][wpos] = nb.y;
            Bs[nxt][lkk + 2][wpos] = nb.z; Bs[nxt][lkk + 3][wpos] = nb.w;
            __syncthreads();
        }
    }

    int e0 = (bx << 7) + tx * 8;
    #pragma unroll
    for (int i = 0; i < 8; i++) {
        int r = (by << 7) + ty * 8 + i;
        float* cp = g_Y + (size_t)r * DDIM + e0;
        #pragma unroll
        for (int jp = 0; jp < 4; jp++) {
            ull tv = totsm[(i * 4 + jp) * 256 + tid];
            unsigned tl, th, al, ah;
            UNPACK2(tl, th, tv);
            UNPACK2(al, ah, acc2[i][jp]);
            float v0 = __fadd_rn(__uint_as_float(tl), __uint_as_float(al));
            float v1 = __fadd_rn(__uint_as_float(th), __uint_as_float(ah));
            cp[2 * jp]     = __fadd_rn(v0, bias[e0 + 2 * jp]);
            cp[2 * jp + 1] = __fadd_rn(v1, bias[e0 + 2 * jp + 1]);
        }
    }
}

// ---------------------------------------------------------------------------
// W2 transpose, 3 partial launches (keeps sgemm at launch index 3 for ncu).
// ---------------------------------------------------------------------------
__global__ void transpose_kernel(const float* __restrict__ W, int part)
{
    __shared__ float tile[32][33];
    int bx = (blockIdx.x + part * 8) << 5, by = blockIdx.y << 5;
    int x = bx + threadIdx.x;
    #pragma unroll
    for (int i = 0; i < 32; i += 8)
        tile[threadIdx.y + i][threadIdx.x] =
            W[(size_t)(by + threadIdx.y + i) * DDIM + x];
    __syncthreads();
    int x2 = by + threadIdx.x;
    #pragma unroll
    for (int i = 0; i < 32; i += 8)
        g_Wt[(size_t)(bx + threadIdx.y + i) * DDIM + x2] =
            tile[threadIdx.x][threadIdx.y + i];
}

// ---------------------------------------------------------------------------
// Fused LayerNorm + LIF (round-15 config): block = 8 positions (32 rows);
// warp 0 runs all 32 strict XLA:CPU stats chains (one row per lane,
// per-row op order unchanged -> bit-exact); warp w runs position w's LIF.
// ---------------------------------------------------------------------------
__global__ __launch_bounds__(256) void ln_lif_kernel(
    const float* __restrict__ gamma, const float* __restrict__ beta,
    float* __restrict__ outp, int final_out)
{
    extern __shared__ float sm[];      // [32 rows][LNP]
    __shared__ float smu[32], srs[32];
    int warp = threadIdx.x >> 5, lane = threadIdx.x & 31;
    int p = (blockIdx.x << 3) + warp;
    int b = p >> 8, l = p & 255;

    float g[24], bb[24], v[24];
    #pragma unroll
    for (int j = 0; j < 24; j++) {
        g[j]  = gamma[lane + (j << 5)];
        bb[j] = beta[lane + (j << 5)];
        v[j]  = 0.f;
    }

    #pragma unroll
    for (int t = 0; t < 4; t++) {
        const float4* row4 = (const float4*)(g_Y + (size_t)(t * NPOS + p) * DDIM);
        float* dst = sm + ((warp << 2) + t) * LNP;
        #pragma unroll
        for (int j = 0; j < 6; j++) {
            float4 x4 = row4[lane + (j << 5)];
            *(float4*)(dst + 4 * (lane + (j << 5))) = x4;
        }
    }
    __syncthreads();

    if (warp == 0) {
        const float* mrow = sm + lane * LNP;
        float acc = 0.f;
        #pragma unroll 8
        for (int d = 0; d < DDIM; d++)
            acc = __fadd_rn(acc, mrow[d]);
        float mu = __fdiv_rn(acc, 768.0f);
        float ssq = 0.f;
        #pragma unroll 8
        for (int d = 0; d < DDIM; d++) {
            float df = __fadd_rn(mrow[d], -mu);
            ssq = __fadd_rn(ssq, __fmul_rn(df, df));
        }
        float var = __fdiv_rn(ssq, 768.0f);
        smu[lane] = mu;
        srs[lane] = __fdiv_rn(1.0f, __fsqrt_rn(__fadd_rn(var, 1e-5f)));
    }
    __syncthreads();

    for (int t = 0; t < 4; t++) {
        int r = t * NPOS + p;
        const float* row = sm + ((warp << 2) + t) * LNP;
        float mu   = smu[(warp << 2) + t];
        float rstd = srs[(warp << 2) + t];

        if (final_out) {
            float* dst = outp + (size_t)((((b << 2) + t) << 8) + l) * DDIM;
            #pragma unroll
            for (int j = 0; j < 24; j++) {
                int d = lane + (j << 5);
                float h = __fadd_rn(
                    __fmul_rn(__fmul_rn(__fadd_rn(row[d], -mu), rstd), g[j]), bb[j]);
                float dlt = __fmul_rn(__fadd_rn(h, -v[j]), 0.5f);
                v[j] = __fadd_rn(v[j], dlt);
                float s = (v[j] >= 1.0f) ? 1.0f : 0.0f;
                dst[d] = s;
                v[j] = __fmul_rn(v[j], __fadd_rn(1.0f, -s));
            }
        } else {
            uint16_t* ip = g_idx + (size_t)r * DDIM;
            int base = 0, c1 = 0, c2 = 0;
            #pragma unroll
            for (int j = 0; j < 24; j++) {      // chunk j covers d=[32j,32j+32)
                int d = lane + (j << 5);
                float h = __fadd_rn(
                    __fmul_rn(__fmul_rn(__fadd_rn(row[d], -mu), rstd), g[j]), bb[j]);
                float dlt = __fmul_rn(__fadd_rn(h, -v[j]), 0.5f);
                v[j] = __fadd_rn(v[j], dlt);
                float s = (v[j] >= 1.0f) ? 1.0f : 0.0f;
                unsigned msk = __ballot_sync(0xffffffffu, s == 1.0f);
                if (s == 1.0f) {
                    int pos = base + __popc(msk & ((1u << lane) - 1u));
                    ip[pos] = (uint16_t)d;
                }
                base += __popc(msk);
                v[j] = __fmul_rn(v[j], __fadd_rn(1.0f, -s));
                if (j == 9)  c1 = base;   // d<320 boundary
                if (j == 19) c2 = base;   // d<640 boundary
            }
            if (lane == 0) g_cnt[r] = make_int4(c1, c2, base, 0);
        }
    }
}

// ---------------------------------------------------------------------------
// Sparse layer-2 GEMM (round-15 config): one warp per (row, e-half).
// ---------------------------------------------------------------------------
__global__ __launch_bounds__(256) void spmm_kernel(const float* __restrict__ bias)
{
    int warp = threadIdx.x >> 5, lane = threadIdx.x & 31;
    int gw = (blockIdx.x << 3) + warp;
    int r = gw >> 1;
    int eoff = (gw & 1) * 96;

    int4 cnt = g_cnt[r];
    int bounds[4] = {0, cnt.x, cnt.y, cnt.z};
    const uint16_t* idx = g_idx + (size_t)r * DDIM;

    float4 tot[3];
    #pragma unroll
    for (int j = 0; j < 3; j++) tot[j] = make_float4(0.f, 0.f, 0.f, 0.f);

    #pragma unroll
    for (int pnl = 0; pnl < 3; pnl++) {
        float4 pan[3];
        #pragma unroll
        for (int j = 0; j < 3; j++) pan[j] = make_float4(0.f, 0.f, 0.f, 0.f);
        int lo = bounds[pnl], hi = bounds[pnl + 1];
        for (int kb = lo; kb < hi; kb += 32) {
            int n = min(32, hi - kb);
            int myd = (kb + lane < hi) ? (int)idx[kb + lane] : 0;
            for (int kk = 0; kk < n; kk++) {
                int d = __shfl_sync(0xffffffffu, myd, kk);
                const float4* w = (const float4*)(g_Wt + d * DDIM) + eoff;
                #pragma unroll
                for (int j = 0; j < 3; j++) {
                    float4 w4 = w[lane + (j << 5)];
                    pan[j].x = __fadd_rn(pan[j].x, w4.x);
                    pan[j].y = __fadd_rn(pan[j].y, w4.y);
                    pan[j].z = __fadd_rn(pan[j].z, w4.z);
                    pan[j].w = __fadd_rn(pan[j].w, w4.w);
                }
            }
        }
        #pragma unroll
        for (int j = 0; j < 3; j++) {
            tot[j].x = __fadd_rn(tot[j].x, pan[j].x);
            tot[j].y = __fadd_rn(tot[j].y, pan[j].y);
            tot[j].z = __fadd_rn(tot[j].z, pan[j].z);
            tot[j].w = __fadd_rn(tot[j].w, pan[j].w);
        }
    }

    float4* orow = (float4*)(g_Y + (size_t)r * DDIM) + eoff;
    const float4* b4 = (const float4*)bias + eoff;
    #pragma unroll
    for (int j = 0; j < 3; j++) {
        int e4 = lane + (j << 5);
        float4 bbv = b4[e4];
        float4 o;
        o.x = __fadd_rn(tot[j].x, bbv.x);
        o.y = __fadd_rn(tot[j].y, bbv.y);
        o.z = __fadd_rn(tot[j].z, bbv.z);
        o.w = __fadd_rn(tot[j].w, bbv.w);
        orow[e4] = o;
    }
}

// ---------------------------------------------------------------------------
extern "C" void kernel_launch(void* const* d_in, const int* in_sizes, int n_in,
                              void* d_out, int out_size)
{
    const float* x   = (const float*)d_in[0];
    const float* W1  = (const float*)d_in[1];
    const float* b1  = (const float*)d_in[2];
    const float* g1  = (const float*)d_in[3];
    const float* be1 = (const float*)d_in[4];
    const float* W2  = (const float*)d_in[5];
    const float* b2  = (const float*)d_in[6];
    const float* g2  = (const float*)d_in[7];
    const float* be2 = (const float*)d_in[8];
    float* out = (float*)d_out;

    const int SG_SMEM = 32 * 256 * 8;       // 65536 B (sgemm tot partials)
    const int LN_SMEM = 32 * LNP * 4;       // 99328 B (32 rows)
    cudaFuncSetAttribute(sgemm_kernel,
                         cudaFuncAttributeMaxDynamicSharedMemorySize, SG_SMEM);
    cudaFuncSetAttribute(ln_lif_kernel,
                         cudaFuncAttributeMaxDynamicSharedMemorySize, LN_SMEM);

    dim3 gg(DDIM / 128, MTOT / 128);   // (6, 256)

    transpose_kernel<<<dim3(8, 24), dim3(32, 8)>>>(W2, 0);
    transpose_kernel<<<dim3(8, 24), dim3(32, 8)>>>(W2, 1);
    transpose_kernel<<<dim3(8, 24), dim3(32, 8)>>>(W2, 2);
    sgemm_kernel<<<gg, 256, SG_SMEM>>>(x, W1, b1);                // ncu idx 3
    ln_lif_kernel<<<NPOS / 8, 256, LN_SMEM>>>(g1, be1, nullptr, 0);
    spmm_kernel<<<MTOT / 4, 256>>>(b2);
    ln_lif_kernel<<<NPOS / 8, 256, LN_SMEM>>>(g2, be2, out, 1);
}